// round 1
// baseline (speedup 1.0000x reference)
#include <cuda_runtime.h>
#include <math.h>

#define NB 4
#define CD 256
#define DD 256
#define LL 4096
#define BN_EPS 1e-4f

// ---------------- scratch (device globals; no allocation allowed) ----------
__device__ float g_Q[NB * LL * DD];
__device__ float g_K[NB * LL * DD];
__device__ float g_V[NB * LL * DD];
__device__ float g_S[(size_t)NB * LL * LL];   // scores / probs (256 MB)
__device__ float g_O[NB * LL * DD];
__device__ float g_Y[NB * CD * LL];
__device__ float g_sA[CD];                    // gamma * rstd
__device__ float g_sB[CD];                    // beta - mean * gamma * rstd

// Tile config: BM=128, BN=64, BK=16, 256 threads, 8x4 outputs per thread.
#define TBM 128
#define TBN 64
#define TBK 16
#define APAD 132   // 128 + 4 (16B-aligned rows: 132*4 = 528 = 33*16)
#define BPAD 68    // 64 + 4  (68*4 = 272 = 17*16)

// ---------------- QKV projection: Out[n][l][d] = sum_c W[d][c] * x[n][c][l]
__global__ void proj_kernel(const float* __restrict__ x,
                            const float* __restrict__ Wq,
                            const float* __restrict__ Wk,
                            const float* __restrict__ Wv) {
    __shared__ __align__(16) float As[TBK][APAD];
    __shared__ __align__(16) float Bs[TBK][BPAD];
    int z = blockIdx.z;            // n*3 + which
    int n = z / 3, w = z - n * 3;
    const float* W = (w == 0) ? Wq : (w == 1) ? Wk : Wv;
    float* Out = (w == 0) ? g_Q : (w == 1) ? g_K : g_V;
    int l0 = blockIdx.x * TBM;
    int d0 = blockIdx.y * TBN;
    const float* xb = x + n * CD * LL;
    int tid = threadIdx.x;
    int tx = tid & 15, ty = tid >> 4;
    float acc[8][4] = {};
    for (int c0 = 0; c0 < CD; c0 += TBK) {
        #pragma unroll
        for (int t = 0; t < 8; t++) {
            int i = t * 256 + tid;
            int mm = i & 127, kk = i >> 7;
            As[kk][mm] = xb[(c0 + kk) * LL + l0 + mm];     // contiguous in l
        }
        #pragma unroll
        for (int t = 0; t < 4; t++) {
            int i = t * 256 + tid;
            int kk = i & 15, dd = i >> 4;
            Bs[kk][dd] = W[(d0 + dd) * CD + c0 + kk];      // contiguous in c
        }
        __syncthreads();
        #pragma unroll
        for (int kk = 0; kk < TBK; kk++) {
            float4 b4 = *(const float4*)&Bs[kk][tx * 4];
            float4 a0 = *(const float4*)&As[kk][ty * 8];
            float4 a1 = *(const float4*)&As[kk][ty * 8 + 4];
            float av[8] = {a0.x, a0.y, a0.z, a0.w, a1.x, a1.y, a1.z, a1.w};
            float bv[4] = {b4.x, b4.y, b4.z, b4.w};
            #pragma unroll
            for (int i = 0; i < 8; i++)
                #pragma unroll
                for (int j = 0; j < 4; j++)
                    acc[i][j] += av[i] * bv[j];
        }
        __syncthreads();
    }
    float* ob = Out + n * LL * DD;
    #pragma unroll
    for (int i = 0; i < 8; i++) {
        float4 v = make_float4(acc[i][0], acc[i][1], acc[i][2], acc[i][3]);
        *(float4*)&ob[(l0 + ty * 8 + i) * DD + d0 + tx * 4] = v;
    }
}

// ---------------- scores: S[n][l][m] = scale * sum_d Q[l][d] K[m][d]  (NT)
__global__ void scores_kernel() {
    __shared__ __align__(16) float As[TBK][APAD];
    __shared__ __align__(16) float Bs[TBK][BPAD];
    int n = blockIdx.z;
    int l0 = blockIdx.x * TBM;
    int m0 = blockIdx.y * TBN;
    const float* Qb = g_Q + n * LL * DD;
    const float* Kb = g_K + n * LL * DD;
    int tid = threadIdx.x;
    int tx = tid & 15, ty = tid >> 4;
    float acc[8][4] = {};
    for (int d0 = 0; d0 < DD; d0 += TBK) {
        #pragma unroll
        for (int t = 0; t < 8; t++) {
            int i = t * 256 + tid;
            As[i & 15][i >> 4] = Qb[(l0 + (i >> 4)) * DD + d0 + (i & 15)];
        }
        #pragma unroll
        for (int t = 0; t < 4; t++) {
            int i = t * 256 + tid;
            Bs[i & 15][i >> 4] = Kb[(m0 + (i >> 4)) * DD + d0 + (i & 15)];
        }
        __syncthreads();
        #pragma unroll
        for (int kk = 0; kk < TBK; kk++) {
            float4 b4 = *(const float4*)&Bs[kk][tx * 4];
            float4 a0 = *(const float4*)&As[kk][ty * 8];
            float4 a1 = *(const float4*)&As[kk][ty * 8 + 4];
            float av[8] = {a0.x, a0.y, a0.z, a0.w, a1.x, a1.y, a1.z, a1.w};
            float bv[4] = {b4.x, b4.y, b4.z, b4.w};
            #pragma unroll
            for (int i = 0; i < 8; i++)
                #pragma unroll
                for (int j = 0; j < 4; j++)
                    acc[i][j] += av[i] * bv[j];
        }
        __syncthreads();
    }
    float* Sb = g_S + (size_t)n * LL * LL;
    const float scale = 0.0625f;  // 1/sqrt(256)
    #pragma unroll
    for (int i = 0; i < 8; i++) {
        float4 v = make_float4(acc[i][0] * scale, acc[i][1] * scale,
                               acc[i][2] * scale, acc[i][3] * scale);
        *(float4*)&Sb[(size_t)(l0 + ty * 8 + i) * LL + m0 + tx * 4] = v;
    }
}

// ---------------- softmax over rows of S (length 4096)
__global__ void softmax_kernel() {
    int row = blockIdx.x;           // 0 .. NB*LL-1
    int n = row >> 12;
    int l = row & 4095;
    float* p = g_S + (size_t)n * LL * LL + (size_t)l * LL;
    int tid = threadIdx.x;          // 256 threads, 16 elems each
    float v[16];
    float mx = -3.4e38f;
    #pragma unroll
    for (int i = 0; i < 16; i++) { v[i] = p[i * 256 + tid]; mx = fmaxf(mx, v[i]); }
    __shared__ float red[8];
    #pragma unroll
    for (int o = 16; o; o >>= 1) mx = fmaxf(mx, __shfl_xor_sync(0xffffffffu, mx, o));
    if ((tid & 31) == 0) red[tid >> 5] = mx;
    __syncthreads();
    mx = red[0];
    #pragma unroll
    for (int i = 1; i < 8; i++) mx = fmaxf(mx, red[i]);
    float s = 0.f;
    #pragma unroll
    for (int i = 0; i < 16; i++) { v[i] = expf(v[i] - mx); s += v[i]; }
    #pragma unroll
    for (int o = 16; o; o >>= 1) s += __shfl_xor_sync(0xffffffffu, s, o);
    __syncthreads();
    if ((tid & 31) == 0) red[tid >> 5] = s;
    __syncthreads();
    float tot = 0.f;
    #pragma unroll
    for (int i = 0; i < 8; i++) tot += red[i];
    float inv = 1.0f / tot;
    #pragma unroll
    for (int i = 0; i < 16; i++) p[i * 256 + tid] = v[i] * inv;
}

// ---------------- attn @ V: O[n][l][d] = sum_m P[l][m] V[m][d]  (NN)
__global__ void av_kernel() {
    __shared__ __align__(16) float As[TBK][APAD];
    __shared__ __align__(16) float Bs[TBK][BPAD];
    int n = blockIdx.z;
    int l0 = blockIdx.x * TBM;
    int d0 = blockIdx.y * TBN;
    const float* Pb = g_S + (size_t)n * LL * LL;
    const float* Vb = g_V + n * LL * DD;
    int tid = threadIdx.x;
    int tx = tid & 15, ty = tid >> 4;
    float acc[8][4] = {};
    for (int m0 = 0; m0 < LL; m0 += TBK) {
        #pragma unroll
        for (int t = 0; t < 8; t++) {
            int i = t * 256 + tid;
            As[i & 15][i >> 4] = Pb[(size_t)(l0 + (i >> 4)) * LL + m0 + (i & 15)];
        }
        #pragma unroll
        for (int t = 0; t < 4; t++) {
            int i = t * 256 + tid;
            int dd = i & 63, kk = i >> 6;
            Bs[kk][dd] = Vb[(m0 + kk) * DD + d0 + dd];
        }
        __syncthreads();
        #pragma unroll
        for (int kk = 0; kk < TBK; kk++) {
            float4 b4 = *(const float4*)&Bs[kk][tx * 4];
            float4 a0 = *(const float4*)&As[kk][ty * 8];
            float4 a1 = *(const float4*)&As[kk][ty * 8 + 4];
            float av[8] = {a0.x, a0.y, a0.z, a0.w, a1.x, a1.y, a1.z, a1.w};
            float bv[4] = {b4.x, b4.y, b4.z, b4.w};
            #pragma unroll
            for (int i = 0; i < 8; i++)
                #pragma unroll
                for (int j = 0; j < 4; j++)
                    acc[i][j] += av[i] * bv[j];
        }
        __syncthreads();
    }
    float* ob = g_O + n * LL * DD;
    #pragma unroll
    for (int i = 0; i < 8; i++) {
        float4 v = make_float4(acc[i][0], acc[i][1], acc[i][2], acc[i][3]);
        *(float4*)&ob[(l0 + ty * 8 + i) * DD + d0 + tx * 4] = v;
    }
}

// ---------------- output proj: Y[n][c][l] = sum_d Wo[c][d] O[n][l][d]  (NT)
__global__ void wo_kernel(const float* __restrict__ Wo) {
    __shared__ __align__(16) float As[TBK][APAD];
    __shared__ __align__(16) float Bs[TBK][BPAD];
    int n = blockIdx.z;
    int c0 = blockIdx.x * TBM;   // over C=256 -> 2 tiles
    int l0 = blockIdx.y * TBN;   // over L=4096 -> 64 tiles
    const float* Ob = g_O + n * LL * DD;
    int tid = threadIdx.x;
    int tx = tid & 15, ty = tid >> 4;
    float acc[8][4] = {};
    for (int d0 = 0; d0 < DD; d0 += TBK) {
        #pragma unroll
        for (int t = 0; t < 8; t++) {
            int i = t * 256 + tid;
            As[i & 15][i >> 4] = Wo[(c0 + (i >> 4)) * DD + d0 + (i & 15)];
        }
        #pragma unroll
        for (int t = 0; t < 4; t++) {
            int i = t * 256 + tid;
            Bs[i & 15][i >> 4] = Ob[(l0 + (i >> 4)) * DD + d0 + (i & 15)];
        }
        __syncthreads();
        #pragma unroll
        for (int kk = 0; kk < TBK; kk++) {
            float4 b4 = *(const float4*)&Bs[kk][tx * 4];
            float4 a0 = *(const float4*)&As[kk][ty * 8];
            float4 a1 = *(const float4*)&As[kk][ty * 8 + 4];
            float av[8] = {a0.x, a0.y, a0.z, a0.w, a1.x, a1.y, a1.z, a1.w};
            float bv[4] = {b4.x, b4.y, b4.z, b4.w};
            #pragma unroll
            for (int i = 0; i < 8; i++)
                #pragma unroll
                for (int j = 0; j < 4; j++)
                    acc[i][j] += av[i] * bv[j];
        }
        __syncthreads();
    }
    float* Yb = g_Y + n * CD * LL;
    #pragma unroll
    for (int i = 0; i < 8; i++) {
        float4 v = make_float4(acc[i][0], acc[i][1], acc[i][2], acc[i][3]);
        *(float4*)&Yb[(c0 + ty * 8 + i) * LL + l0 + tx * 4] = v;
    }
}

// ---------------- BatchNorm stats per channel (fp64 accumulation)
__global__ void bnstats_kernel(const float* __restrict__ gamma,
                               const float* __restrict__ beta) {
    int c = blockIdx.x;
    int tid = threadIdx.x;
    double s = 0.0, sq = 0.0;
    for (int i = tid; i < NB * LL; i += 256) {
        int n = i >> 12, l = i & 4095;
        float y = g_Y[n * CD * LL + c * LL + l];
        s += (double)y;
        sq += (double)y * (double)y;
    }
    __shared__ double rs[8], rq[8];
    #pragma unroll
    for (int o = 16; o; o >>= 1) {
        s  += __shfl_xor_sync(0xffffffffu, s, o);
        sq += __shfl_xor_sync(0xffffffffu, sq, o);
    }
    if ((tid & 31) == 0) { rs[tid >> 5] = s; rq[tid >> 5] = sq; }
    __syncthreads();
    if (tid == 0) {
        double ts = 0.0, tq = 0.0;
        #pragma unroll
        for (int i = 0; i < 8; i++) { ts += rs[i]; tq += rq[i]; }
        double cnt = (double)(NB * LL);
        double mean = ts / cnt;
        double var = tq / cnt - mean * mean;
        float a = gamma[c] * rsqrtf((float)var + BN_EPS);
        g_sA[c] = a;
        g_sB[c] = beta[c] - (float)mean * a;
    }
}

// ---------------- residual + affine BN apply
__global__ void final_kernel(const float* __restrict__ x, float* __restrict__ out) {
    int e = (blockIdx.x * 256 + threadIdx.x) * 4;   // 4,194,304 total elems
    int c = (e >> 12) & 255;
    float a = g_sA[c], b = g_sB[c];
    float4 xv = *(const float4*)&x[e];
    float4 yv = *(const float4*)&g_Y[e];
    float4 o;
    o.x = xv.x + yv.x * a + b;
    o.y = xv.y + yv.y * a + b;
    o.z = xv.z + yv.z * a + b;
    o.w = xv.w + yv.w * a + b;
    *(float4*)&out[e] = o;
}

extern "C" void kernel_launch(void* const* d_in, const int* in_sizes, int n_in,
                              void* d_out, int out_size) {
    const float* x     = (const float*)d_in[0];
    const float* Wq    = (const float*)d_in[1];
    const float* Wk    = (const float*)d_in[2];
    const float* Wv    = (const float*)d_in[3];
    const float* Wo    = (const float*)d_in[4];
    const float* gamma = (const float*)d_in[5];
    const float* beta  = (const float*)d_in[6];
    float* out = (float*)d_out;

    proj_kernel  <<<dim3(LL / TBM, DD / TBN, NB * 3), 256>>>(x, Wq, Wk, Wv);
    scores_kernel<<<dim3(LL / TBM, LL / TBN, NB), 256>>>();
    softmax_kernel<<<NB * LL, 256>>>();
    av_kernel    <<<dim3(LL / TBM, DD / TBN, NB), 256>>>();
    wo_kernel    <<<dim3(CD / TBM, LL / TBN, NB), 256>>>(Wo);
    bnstats_kernel<<<CD, 256>>>(gamma, beta);
    final_kernel <<<(NB * CD * LL) / 4 / 256, 256>>>(x, out);
}

// round 4
// speedup vs baseline: 1.4535x; 1.4535x over previous
#include <cuda_runtime.h>
#include <cuda_bf16.h>
#include <math.h>
#include <stdint.h>

#define NB 4
#define CD 256
#define DD 256
#define LL 4096
#define BN_EPS 1e-4f

// ---------------- scratch (device globals; no allocation allowed) ----------
__device__ __nv_bfloat16 g_Qhi[NB * LL * DD], g_Qlo[NB * LL * DD];
__device__ __nv_bfloat16 g_Khi[NB * LL * DD], g_Klo[NB * LL * DD];
__device__ __nv_bfloat16 g_Vthi[NB * DD * LL], g_Vtlo[NB * DD * LL];   // V^T [n][d][l]
__device__ float g_S[(size_t)NB * LL * LL];                            // fp32 scores
__device__ __nv_bfloat16 g_Phi[(size_t)NB * LL * LL];                  // probs hi
__device__ __nv_bfloat16 g_Plo[(size_t)NB * LL * LL];                  // probs lo
__device__ float g_O[NB * LL * DD];
__device__ float g_Y[NB * CD * LL];
__device__ float g_sA[CD], g_sB[CD];

// =====================================================================
// PTX helpers (sm_80-class only: cp.async, ldmatrix, mma.sync)
// =====================================================================
__device__ __forceinline__ uint32_t smem_u32(const void* p) {
    uint32_t a;
    asm("{ .reg .u64 t; cvta.to.shared.u64 t, %1; cvt.u32.u64 %0, t; }" : "=r"(a) : "l"(p));
    return a;
}
#define CP16(dst, src) \
    asm volatile("cp.async.cg.shared.global [%0], [%1], 16;" :: "r"(dst), "l"(src))
#define CP_COMMIT() asm volatile("cp.async.commit_group;" ::: "memory")
#define CP_WAIT1()  asm volatile("cp.async.wait_group 1;" ::: "memory")
#define CP_WAIT0()  asm volatile("cp.async.wait_group 0;" ::: "memory")

#define LDSM4(r, addr) \
    asm volatile("ldmatrix.sync.aligned.m8n8.x4.shared.b16 {%0,%1,%2,%3}, [%4];" \
        : "=r"((r)[0]), "=r"((r)[1]), "=r"((r)[2]), "=r"((r)[3]) : "r"(addr))

__device__ __forceinline__ void mma_bf16(float* c, const uint32_t* a, const uint32_t* b) {
    asm volatile(
        "mma.sync.aligned.m16n8k16.row.col.f32.bf16.bf16.f32 "
        "{%0,%1,%2,%3}, {%4,%5,%6,%7}, {%8,%9}, {%0,%1,%2,%3};"
        : "+f"(c[0]), "+f"(c[1]), "+f"(c[2]), "+f"(c[3])
        : "r"(a[0]), "r"(a[1]), "r"(a[2]), "r"(a[3]), "r"(b[0]), "r"(b[1]));
}

__device__ __forceinline__ void split1(float a, __nv_bfloat16& h, __nv_bfloat16& l) {
    h = __float2bfloat16(a);
    l = __float2bfloat16(a - __bfloat162float(h));
}
__device__ __forceinline__ uint32_t pack2(__nv_bfloat16 a, __nv_bfloat16 b) {
    return (uint32_t)__bfloat16_as_ushort(a) | ((uint32_t)__bfloat16_as_ushort(b) << 16);
}

// =====================================================================
// bf16x3 GEMM: C[M,N] = scale * (Ahi+Alo)[M,K] * (Bhi+Blo)[N,K]^T
// (drops lo*lo term; rel err ~2^-16). 128x128 tile, K-chunk 64, 2-stage
// cp.async pipeline, 8 warps each computing 32x64 via HMMA m16n8k16.
// =====================================================================
#define RS 144                 // smem row stride (bytes): 128B data + 16B pad
#define MAT_SZ (128 * RS)      // 18432 B per matrix per stage
#define STAGE (4 * MAT_SZ)     // Ahi,Alo,Bhi,Blo
#define GSMEM (2 * STAGE)      // 147456 B

__global__ void __launch_bounds__(256, 1)
gemm_bf16x3(const __nv_bfloat16* __restrict__ Ahi, const __nv_bfloat16* __restrict__ Alo,
            const __nv_bfloat16* __restrict__ Bhi, const __nv_bfloat16* __restrict__ Blo,
            float* __restrict__ C, int lda, int ldb, int ldc, int K, float scale,
            size_t sA, size_t sB, size_t sC)
{
    extern __shared__ char smem[];
    uint32_t sb = smem_u32(smem);
    int tid = threadIdx.x, lane = tid & 31, wid = tid >> 5;
    Ahi += blockIdx.z * sA;  Alo += blockIdx.z * sA;
    Bhi += blockIdx.z * sB;  Blo += blockIdx.z * sB;
    C   += blockIdx.z * sC;
    int m0 = blockIdx.x * 128, n0 = blockIdx.y * 128;

    // producer mapping: thread -> (row, half-row of 32 elems)
    int pr = tid >> 1, ph = tid & 1;
    const __nv_bfloat16* pA0 = Ahi + (size_t)(m0 + pr) * lda + ph * 32;
    const __nv_bfloat16* pA1 = Alo + (size_t)(m0 + pr) * lda + ph * 32;
    const __nv_bfloat16* pB0 = Bhi + (size_t)(n0 + pr) * ldb + ph * 32;
    const __nv_bfloat16* pB1 = Blo + (size_t)(n0 + pr) * ldb + ph * 32;
    uint32_t sdst = (uint32_t)(pr * RS + ph * 64);

    auto loadChunk = [&](int c, int stg) {
        uint32_t st = sb + stg * STAGE + sdst;
        int k0 = c << 6;
        #pragma unroll
        for (int g = 0; g < 4; g++) CP16(st + 0 * MAT_SZ + g * 16, (const char*)(pA0 + k0) + g * 16);
        #pragma unroll
        for (int g = 0; g < 4; g++) CP16(st + 1 * MAT_SZ + g * 16, (const char*)(pA1 + k0) + g * 16);
        #pragma unroll
        for (int g = 0; g < 4; g++) CP16(st + 2 * MAT_SZ + g * 16, (const char*)(pB0 + k0) + g * 16);
        #pragma unroll
        for (int g = 0; g < 4; g++) CP16(st + 3 * MAT_SZ + g * 16, (const char*)(pB1 + k0) + g * 16);
        CP_COMMIT();
    };

    // consumer mapping: warp -> 32x64 output tile
    int wm = (wid & 3) * 32;          // m offset within 128
    int wn = (wid >> 2) * 64;         // n offset within 128
    uint32_t aLane = (uint32_t)((wm + (lane & 15)) * RS + ((lane >> 4) & 1) * 16);
    uint32_t bLane = (uint32_t)((wn + ((lane >> 4) & 1) * 8 + (lane & 7)) * RS + ((lane >> 3) & 1) * 16);

    float acc[64];
    #pragma unroll
    for (int i = 0; i < 64; i++) acc[i] = 0.f;

    int NC = K >> 6;
    loadChunk(0, 0);
    for (int c = 0; c < NC; c++) {
        int cur = c & 1;
        if (c + 1 < NC) { loadChunk(c + 1, cur ^ 1); CP_WAIT1(); }
        else            { CP_WAIT0(); }
        __syncthreads();

        uint32_t st = sb + cur * STAGE;
        uint32_t aB = st + aLane;
        uint32_t bB = st + 2 * MAT_SZ + bLane;
        #pragma unroll
        for (int ks = 0; ks < 4; ks++) {
            uint32_t a = aB + ks * 32;
            uint32_t ah0[4], ah1[4], al0[4], al1[4];
            LDSM4(ah0, a);
            LDSM4(ah1, a + 16 * RS);
            LDSM4(al0, a + MAT_SZ);
            LDSM4(al1, a + MAT_SZ + 16 * RS);
            #pragma unroll
            for (int np = 0; np < 4; np++) {
                uint32_t b = bB + np * 16 * RS + ks * 32;
                uint32_t bh[4], bl[4];
                LDSM4(bh, b);
                LDSM4(bl, b + MAT_SZ);
                #pragma unroll
                for (int sub = 0; sub < 2; sub++) {
                    int nt = np * 2 + sub;
                    float* c0 = acc + (0 * 8 + nt) * 4;
                    float* c1 = acc + (1 * 8 + nt) * 4;
                    const uint32_t* bhp = bh + sub * 2;
                    const uint32_t* blp = bl + sub * 2;
                    mma_bf16(c0, ah0, bhp);
                    mma_bf16(c0, ah0, blp);
                    mma_bf16(c0, al0, bhp);
                    mma_bf16(c1, ah1, bhp);
                    mma_bf16(c1, ah1, blp);
                    mma_bf16(c1, al1, bhp);
                }
            }
        }
        __syncthreads();
    }

    // epilogue
    int r0 = m0 + wm + (lane >> 2);
    int cbase = n0 + wn + (lane & 3) * 2;
    #pragma unroll
    for (int mt = 0; mt < 2; mt++) {
        #pragma unroll
        for (int nt = 0; nt < 8; nt++) {
            float* cc = acc + (mt * 8 + nt) * 4;
            int row = r0 + mt * 16;
            int col = cbase + nt * 8;
            float2 v0 = make_float2(cc[0] * scale, cc[1] * scale);
            float2 v1 = make_float2(cc[2] * scale, cc[3] * scale);
            *(float2*)&C[(size_t)row * ldc + col]       = v0;
            *(float2*)&C[(size_t)(row + 8) * ldc + col] = v1;
        }
    }
}

// =====================================================================
// SIMT kernels
// =====================================================================
#define TBM 128
#define TBN 64
#define TBK 16
#define APAD 132
#define BPAD 68

// QKV projection -> split bf16 outputs. Out[n][l][d] = sum_c W[d][c] x[n][c][l]
__global__ void proj_kernel(const float* __restrict__ x,
                            const float* __restrict__ Wq,
                            const float* __restrict__ Wk,
                            const float* __restrict__ Wv) {
    __shared__ __align__(16) float As[TBK][APAD];
    __shared__ __align__(16) float Bs[TBK][BPAD];
    int z = blockIdx.z;
    int n = z / 3, w = z - n * 3;
    const float* W = (w == 0) ? Wq : (w == 1) ? Wk : Wv;
    int l0 = blockIdx.x * TBM;
    int d0 = blockIdx.y * TBN;
    const float* xb = x + n * CD * LL;
    int tid = threadIdx.x;
    int tx = tid & 15, ty = tid >> 4;
    float acc[8][4] = {};
    for (int c0 = 0; c0 < CD; c0 += TBK) {
        #pragma unroll
        for (int t = 0; t < 8; t++) {
            int i = t * 256 + tid;
            As[i >> 7][i & 127] = xb[(c0 + (i >> 7)) * LL + l0 + (i & 127)];
        }
        #pragma unroll
        for (int t = 0; t < 4; t++) {
            int i = t * 256 + tid;
            Bs[i & 15][i >> 4] = W[(d0 + (i >> 4)) * CD + c0 + (i & 15)];
        }
        __syncthreads();
        #pragma unroll
        for (int kk = 0; kk < TBK; kk++) {
            float4 b4 = *(const float4*)&Bs[kk][tx * 4];
            float4 a0 = *(const float4*)&As[kk][ty * 8];
            float4 a1 = *(const float4*)&As[kk][ty * 8 + 4];
            float av[8] = {a0.x, a0.y, a0.z, a0.w, a1.x, a1.y, a1.z, a1.w};
            float bv[4] = {b4.x, b4.y, b4.z, b4.w};
            #pragma unroll
            for (int i = 0; i < 8; i++)
                #pragma unroll
                for (int j = 0; j < 4; j++)
                    acc[i][j] += av[i] * bv[j];
        }
        __syncthreads();
    }
    if (w == 2) {   // V transposed, split
        __nv_bfloat16* vh = g_Vthi + (size_t)n * DD * LL;
        __nv_bfloat16* vl = g_Vtlo + (size_t)n * DD * LL;
        #pragma unroll
        for (int j = 0; j < 4; j++)
            #pragma unroll
            for (int i = 0; i < 8; i++) {
                __nv_bfloat16 h, l;
                split1(acc[i][j], h, l);
                size_t idx = (size_t)(d0 + tx * 4 + j) * LL + l0 + ty * 8 + i;
                vh[idx] = h; vl[idx] = l;
            }
    } else {
        __nv_bfloat16* oh = ((w == 0) ? g_Qhi : g_Khi) + (size_t)n * LL * DD;
        __nv_bfloat16* ol = ((w == 0) ? g_Qlo : g_Klo) + (size_t)n * LL * DD;
        #pragma unroll
        for (int i = 0; i < 8; i++) {
            __nv_bfloat16 h[4], l[4];
            #pragma unroll
            for (int j = 0; j < 4; j++) split1(acc[i][j], h[j], l[j]);
            size_t base = (size_t)(l0 + ty * 8 + i) * DD + d0 + tx * 4;
            uint2 hv = make_uint2(pack2(h[0], h[1]), pack2(h[2], h[3]));
            uint2 lv = make_uint2(pack2(l[0], l[1]), pack2(l[2], l[3]));
            *(uint2*)&oh[base] = hv;
            *(uint2*)&ol[base] = lv;
        }
    }
}

// softmax over rows of S; writes split bf16 probs
__global__ void softmax_kernel() {
    size_t row = blockIdx.x;
    float* p = g_S + row * LL;
    __nv_bfloat16* ph = g_Phi + row * LL;
    __nv_bfloat16* pl = g_Plo + row * LL;
    int tid = threadIdx.x;                 // 256 threads, 16 contiguous each
    float v[16];
    #pragma unroll
    for (int i = 0; i < 4; i++) {
        float4 t = *(const float4*)&p[tid * 16 + i * 4];
        v[i * 4] = t.x; v[i * 4 + 1] = t.y; v[i * 4 + 2] = t.z; v[i * 4 + 3] = t.w;
    }
    float mx = -3.4e38f;
    #pragma unroll
    for (int i = 0; i < 16; i++) mx = fmaxf(mx, v[i]);
    __shared__ float red[8];
    #pragma unroll
    for (int o = 16; o; o >>= 1) mx = fmaxf(mx, __shfl_xor_sync(0xffffffffu, mx, o));
    if ((tid & 31) == 0) red[tid >> 5] = mx;
    __syncthreads();
    mx = red[0];
    #pragma unroll
    for (int i = 1; i < 8; i++) mx = fmaxf(mx, red[i]);
    float s = 0.f;
    #pragma unroll
    for (int i = 0; i < 16; i++) { v[i] = expf(v[i] - mx); s += v[i]; }
    #pragma unroll
    for (int o = 16; o; o >>= 1) s += __shfl_xor_sync(0xffffffffu, s, o);
    __syncthreads();
    if ((tid & 31) == 0) red[tid >> 5] = s;
    __syncthreads();
    float tot = 0.f;
    #pragma unroll
    for (int i = 0; i < 8; i++) tot += red[i];
    float inv = 1.0f / tot;
    #pragma unroll
    for (int i = 0; i < 8; i++) {
        float a = v[2 * i] * inv, b = v[2 * i + 1] * inv;
        __nv_bfloat16 ha, la, hb, lb;
        split1(a, ha, la); split1(b, hb, lb);
        *(uint32_t*)&ph[tid * 16 + 2 * i] = pack2(ha, hb);
        *(uint32_t*)&pl[tid * 16 + 2 * i] = pack2(la, lb);
    }
}

// output proj: Y[n][c][l] = sum_d Wo[c][d] O[n][l][d]
__global__ void wo_kernel(const float* __restrict__ Wo) {
    __shared__ __align__(16) float As[TBK][APAD];
    __shared__ __align__(16) float Bs[TBK][BPAD];
    int n = blockIdx.z;
    int c0 = blockIdx.x * TBM;
    int l0 = blockIdx.y * TBN;
    const float* Ob = g_O + n * LL * DD;
    int tid = threadIdx.x;
    int tx = tid & 15, ty = tid >> 4;
    float acc[8][4] = {};
    for (int d0 = 0; d0 < DD; d0 += TBK) {
        #pragma unroll
        for (int t = 0; t < 8; t++) {
            int i = t * 256 + tid;
            As[i & 15][i >> 4] = Wo[(c0 + (i >> 4)) * DD + d0 + (i & 15)];
        }
        #pragma unroll
        for (int t = 0; t < 4; t++) {
            int i = t * 256 + tid;
            Bs[i & 15][i >> 4] = Ob[(size_t)(l0 + (i >> 4)) * DD + d0 + (i & 15)];
        }
        __syncthreads();
        #pragma unroll
        for (int kk = 0; kk < TBK; kk++) {
            float4 b4 = *(const float4*)&Bs[kk][tx * 4];
            float4 a0 = *(const float4*)&As[kk][ty * 8];
            float4 a1 = *(const float4*)&As[kk][ty * 8 + 4];
            float av[8] = {a0.x, a0.y, a0.z, a0.w, a1.x, a1.y, a1.z, a1.w};
            float bv[4] = {b4.x, b4.y, b4.z, b4.w};
            #pragma unroll
            for (int i = 0; i < 8; i++)
                #pragma unroll
                for (int j = 0; j < 4; j++)
                    acc[i][j] += av[i] * bv[j];
        }
        __syncthreads();
    }
    float* Yb = g_Y + n * CD * LL;
    #pragma unroll
    for (int i = 0; i < 8; i++) {
        float4 v = make_float4(acc[i][0], acc[i][1], acc[i][2], acc[i][3]);
        *(float4*)&Yb[(size_t)(c0 + ty * 8 + i) * LL + l0 + tx * 4] = v;
    }
}

__global__ void bnstats_kernel(const float* __restrict__ gamma,
                               const float* __restrict__ beta) {
    int c = blockIdx.x;
    int tid = threadIdx.x;
    double s = 0.0, sq = 0.0;
    for (int i = tid; i < NB * LL; i += 256) {
        int n = i >> 12, l = i & 4095;
        float y = g_Y[n * CD * LL + c * LL + l];
        s += (double)y;
        sq += (double)y * (double)y;
    }
    __shared__ double rs[8], rq[8];
    #pragma unroll
    for (int o = 16; o; o >>= 1) {
        s  += __shfl_xor_sync(0xffffffffu, s, o);
        sq += __shfl_xor_sync(0xffffffffu, sq, o);
    }
    if ((tid & 31) == 0) { rs[tid >> 5] = s; rq[tid >> 5] = sq; }
    __syncthreads();
    if (tid == 0) {
        double ts = 0.0, tq = 0.0;
        #pragma unroll
        for (int i = 0; i < 8; i++) { ts += rs[i]; tq += rq[i]; }
        double cnt = (double)(NB * LL);
        double mean = ts / cnt;
        double var = tq / cnt - mean * mean;
        float a = gamma[c] * rsqrtf((float)var + BN_EPS);
        g_sA[c] = a;
        g_sB[c] = beta[c] - (float)mean * a;
    }
}

__global__ void final_kernel(const float* __restrict__ x, float* __restrict__ out) {
    int e = (blockIdx.x * 256 + threadIdx.x) * 4;
    int c = (e >> 12) & 255;
    float a = g_sA[c], b = g_sB[c];
    float4 xv = *(const float4*)&x[e];
    float4 yv = *(const float4*)&g_Y[e];
    float4 o;
    o.x = xv.x + yv.x * a + b;
    o.y = xv.y + yv.y * a + b;
    o.z = xv.z + yv.z * a + b;
    o.w = xv.w + yv.w * a + b;
    *(float4*)&out[e] = o;
}

extern "C" void kernel_launch(void* const* d_in, const int* in_sizes, int n_in,
                              void* d_out, int out_size) {
    const float* x     = (const float*)d_in[0];
    const float* Wq    = (const float*)d_in[1];
    const float* Wk    = (const float*)d_in[2];
    const float* Wv    = (const float*)d_in[3];
    const float* Wo    = (const float*)d_in[4];
    const float* gamma = (const float*)d_in[5];
    const float* beta  = (const float*)d_in[6];
    float* out = (float*)d_out;

    cudaFuncSetAttribute(gemm_bf16x3,
                         cudaFuncAttributeMaxDynamicSharedMemorySize, GSMEM);

    __nv_bfloat16 *Qh, *Ql, *Kh, *Kl, *Vh, *Vl, *Ph, *Pl;
    float *Sp, *Op;
    cudaGetSymbolAddress((void**)&Qh, g_Qhi);
    cudaGetSymbolAddress((void**)&Ql, g_Qlo);
    cudaGetSymbolAddress((void**)&Kh, g_Khi);
    cudaGetSymbolAddress((void**)&Kl, g_Klo);
    cudaGetSymbolAddress((void**)&Vh, g_Vthi);
    cudaGetSymbolAddress((void**)&Vl, g_Vtlo);
    cudaGetSymbolAddress((void**)&Ph, g_Phi);
    cudaGetSymbolAddress((void**)&Pl, g_Plo);
    cudaGetSymbolAddress((void**)&Sp, g_S);
    cudaGetSymbolAddress((void**)&Op, g_O);

    proj_kernel<<<dim3(LL / TBM, DD / TBN, NB * 3), 256>>>(x, Wq, Wk, Wv);

    // scores: S = scale * Q K^T   (M=L, N=L, K=D)
    gemm_bf16x3<<<dim3(LL / 128, LL / 128, NB), 256, GSMEM>>>(
        Qh, Ql, Kh, Kl, Sp, DD, DD, LL, DD, 0.0625f,
        (size_t)LL * DD, (size_t)LL * DD, (size_t)LL * LL);

    softmax_kernel<<<NB * LL, 256>>>();

    // O = P V    (M=L, N=D, K=L); B = V^T rows d, K-major over l
    gemm_bf16x3<<<dim3(LL / 128, DD / 128, NB), 256, GSMEM>>>(
        Ph, Pl, Vh, Vl, Op, LL, LL, DD, LL, 1.0f,
        (size_t)LL * LL, (size_t)DD * LL, (size_t)LL * DD);

    wo_kernel<<<dim3(CD / TBM, LL / TBN, NB), 256>>>(Wo);
    bnstats_kernel<<<CD, 256>>>(gamma, beta);
    final_kernel<<<(NB * CD * LL) / 4 / 256, 256>>>(x, out);
}